// round 2
// baseline (speedup 1.0000x reference)
#include <cuda_runtime.h>
#include <math.h>

// Problem dims (fixed by the dataset)
#define NT 2048      // tokens (B*S)
#define NE 8         // experts
#define ND 1024      // d_model
#define NF 2048      // d_ff
#define TOPK 2

// -------- scratch (alloc-free: __device__ globals) --------
__device__ int   g_cnt[NE];                       // tokens routed to each expert
__device__ int   g_tok[NE * NT];                  // token id per (expert, slot)
__device__ float g_wgt[NE * NT];                  // combine weight per (expert, slot)
__device__ float g_h[(size_t)NE * NT * NF];       // silu(x@W1) activations, 134 MB

// ---------------------------------------------------------------------------
// Kernel 0: zero output + expert counters
// ---------------------------------------------------------------------------
__global__ void k_zero(float* __restrict__ out) {
    int i = blockIdx.x * blockDim.x + threadIdx.x;
    if (i < NT * ND) out[i] = 0.0f;
    if (i < NE) g_cnt[i] = 0;
}

// ---------------------------------------------------------------------------
// Kernel 1: router — softmax over 8 logits, top-2, renormalize, dispatch
// ---------------------------------------------------------------------------
__global__ void k_router(const float* __restrict__ logits) {
    int t = blockIdx.x * blockDim.x + threadIdx.x;
    if (t >= NT) return;
    float l[NE];
#pragma unroll
    for (int e = 0; e < NE; e++) l[e] = logits[t * NE + e];

    // argmax
    int i0 = 0;
#pragma unroll
    for (int e = 1; e < NE; e++) if (l[e] > l[i0]) i0 = e;
    // second argmax
    int i1 = -1; float best = -1e30f;
#pragma unroll
    for (int e = 0; e < NE; e++) {
        if (e != i0 && l[e] > best) { best = l[e]; i1 = e; }
    }
    // renormalized top-2 softmax weights: w0 = p0/(p0+p1) = sigmoid(l0-l1)
    float w0 = 1.0f / (1.0f + expf(l[i1] - l[i0]));
    float w1 = 1.0f - w0;

    int s0 = atomicAdd(&g_cnt[i0], 1);
    g_tok[i0 * NT + s0] = t;
    g_wgt[i0 * NT + s0] = w0;
    int s1 = atomicAdd(&g_cnt[i1], 1);
    g_tok[i1 * NT + s1] = t;
    g_wgt[i1 * NT + s1] = w1;
}

// ---------------------------------------------------------------------------
// Kernel 2: grouped GEMM1 + SiLU
//   H[e, m, n] = silu( sum_k x[tok[e,m], k] * W1[e, k, n] )
//   tiles: BM=64, BN=64, BK=16; 256 threads; 4x4 register micro-tile
// ---------------------------------------------------------------------------
__global__ void k_gemm1(const float* __restrict__ x, const float* __restrict__ W1) {
    const int e   = blockIdx.z;
    const int cnt = g_cnt[e];
    const int m0  = blockIdx.x * 64;
    if (m0 >= cnt) return;
    const int n0  = blockIdx.y * 64;

    __shared__ float As[16][68];   // [k][m], padded
    __shared__ float Bs[16][64];   // [k][n]

    const int tid = threadIdx.x;
    const int ty  = tid >> 4;      // 0..15 -> m group
    const int tx  = tid & 15;      // 0..15 -> n group

    const int*   tok = &g_tok[e * NT];
    const float* W   = W1 + (size_t)e * ND * NF;

    float acc[4][4];
#pragma unroll
    for (int i = 0; i < 4; i++)
#pragma unroll
        for (int j = 0; j < 4; j++) acc[i][j] = 0.0f;

    for (int k0 = 0; k0 < ND; k0 += 16) {
        // load A tile (gathered rows), transposed into As[k][m]
#pragma unroll
        for (int it = 0; it < 4; it++) {
            int i = tid + it * 256;           // 0..1023
            int r = i >> 4, c = i & 15;
            float v = 0.0f;
            int row = m0 + r;
            if (row < cnt) v = x[(size_t)tok[row] * ND + k0 + c];
            As[c][r] = v;
        }
        // load B tile
#pragma unroll
        for (int it = 0; it < 4; it++) {
            int i = tid + it * 256;           // 0..1023
            int r = i >> 6, c = i & 63;
            Bs[r][c] = W[(size_t)(k0 + r) * NF + n0 + c];
        }
        __syncthreads();

#pragma unroll
        for (int k = 0; k < 16; k++) {
            float a[4], b[4];
#pragma unroll
            for (int j = 0; j < 4; j++) a[j] = As[k][ty * 4 + j];
#pragma unroll
            for (int j = 0; j < 4; j++) b[j] = Bs[k][tx * 4 + j];
#pragma unroll
            for (int i = 0; i < 4; i++)
#pragma unroll
                for (int j = 0; j < 4; j++) acc[i][j] = fmaf(a[i], b[j], acc[i][j]);
        }
        __syncthreads();
    }

    float* H = &g_h[(size_t)(e * NT) * NF];
#pragma unroll
    for (int i = 0; i < 4; i++) {
        int row = m0 + ty * 4 + i;
        if (row < cnt) {
#pragma unroll
            for (int j = 0; j < 4; j++) {
                float v = acc[i][j];
                float s = v / (1.0f + expf(-v));   // silu
                H[(size_t)row * NF + n0 + tx * 4 + j] = s;
            }
        }
    }
}

// ---------------------------------------------------------------------------
// Kernel 3: grouped GEMM2 + weighted scatter-combine
//   out[tok[e,m], n] += wgt[e,m] * sum_k H[e, m, k] * W2[e, k, n]
// ---------------------------------------------------------------------------
__global__ void k_gemm2(const float* __restrict__ W2, float* __restrict__ out) {
    const int e   = blockIdx.z;
    const int cnt = g_cnt[e];
    const int m0  = blockIdx.x * 64;
    if (m0 >= cnt) return;
    const int n0  = blockIdx.y * 64;

    __shared__ float As[16][68];
    __shared__ float Bs[16][64];

    const int tid = threadIdx.x;
    const int ty  = tid >> 4;
    const int tx  = tid & 15;

    const float* H = &g_h[(size_t)(e * NT) * NF];
    const float* W = W2 + (size_t)e * NF * ND;

    float acc[4][4];
#pragma unroll
    for (int i = 0; i < 4; i++)
#pragma unroll
        for (int j = 0; j < 4; j++) acc[i][j] = 0.0f;

    for (int k0 = 0; k0 < NF; k0 += 16) {
#pragma unroll
        for (int it = 0; it < 4; it++) {
            int i = tid + it * 256;
            int r = i >> 4, c = i & 15;
            float v = 0.0f;
            int row = m0 + r;
            if (row < cnt) v = H[(size_t)row * NF + k0 + c];
            As[c][r] = v;
        }
#pragma unroll
        for (int it = 0; it < 4; it++) {
            int i = tid + it * 256;
            int r = i >> 6, c = i & 63;
            Bs[r][c] = W[(size_t)(k0 + r) * ND + n0 + c];
        }
        __syncthreads();

#pragma unroll
        for (int k = 0; k < 16; k++) {
            float a[4], b[4];
#pragma unroll
            for (int j = 0; j < 4; j++) a[j] = As[k][ty * 4 + j];
#pragma unroll
            for (int j = 0; j < 4; j++) b[j] = Bs[k][tx * 4 + j];
#pragma unroll
            for (int i = 0; i < 4; i++)
#pragma unroll
                for (int j = 0; j < 4; j++) acc[i][j] = fmaf(a[i], b[j], acc[i][j]);
        }
        __syncthreads();
    }

#pragma unroll
    for (int i = 0; i < 4; i++) {
        int row = m0 + ty * 4 + i;
        if (row < cnt) {
            float w = g_wgt[e * NT + row];
            int   t = g_tok[e * NT + row];
#pragma unroll
            for (int j = 0; j < 4; j++) {
                atomicAdd(&out[(size_t)t * ND + n0 + tx * 4 + j], w * acc[i][j]);
            }
        }
    }
}

// ---------------------------------------------------------------------------
// launch
// ---------------------------------------------------------------------------
extern "C" void kernel_launch(void* const* d_in, const int* in_sizes, int n_in,
                              void* d_out, int out_size) {
    const float* hidden = (const float*)d_in[0];   // [B,S,D] = [T, D]
    const float* logits = (const float*)d_in[1];   // [T, E]
    const float* W1     = (const float*)d_in[2];   // [E, D, F]
    const float* W2     = (const float*)d_in[3];   // [E, F, D]
    float* out = (float*)d_out;                    // [T, D]

    k_zero<<<(NT * ND + 255) / 256, 256>>>(out);
    k_router<<<(NT + 255) / 256, 256>>>(logits);

    dim3 g1(NT / 64, NF / 64, NE);   // (32, 32, 8); blocks past cnt[e] exit early
    k_gemm1<<<g1, 256>>>(hidden, W1);

    dim3 g2(NT / 64, ND / 64, NE);   // (32, 16, 8)
    k_gemm2<<<g2, 256>>>(W2, out);
}

// round 3
// speedup vs baseline: 2.3963x; 2.3963x over previous
#include <cuda_runtime.h>
#include <math.h>
#include <stdint.h>

// Problem dims (fixed by the dataset)
#define NT 2048      // tokens (B*S)
#define NE 8         // experts
#define ND 1024      // d_model
#define NF 2048      // d_ff

// -------- scratch (alloc-free: __device__ globals) --------
__device__ int   g_cnt[NE];
__device__ int   g_tok[NE * NT];
__device__ float g_wgt[NE * NT];
__device__ float g_h[(size_t)NE * NT * NF];   // silu(x@W1), slot-major per expert

// ---------------------------------------------------------------------------
// Kernel 0: zero output + expert counters
// ---------------------------------------------------------------------------
__global__ void k_zero(float4* __restrict__ out) {
    int i = blockIdx.x * blockDim.x + threadIdx.x;
    if (i < NT * ND / 4) out[i] = make_float4(0.f, 0.f, 0.f, 0.f);
    if (i < NE) g_cnt[i] = 0;
}

// ---------------------------------------------------------------------------
// Kernel 1: router — softmax over 8 logits, top-2, renormalize, dispatch
// ---------------------------------------------------------------------------
__global__ void k_router(const float* __restrict__ logits) {
    int t = blockIdx.x * blockDim.x + threadIdx.x;
    if (t >= NT) return;
    float l[NE];
#pragma unroll
    for (int e = 0; e < NE; e++) l[e] = logits[t * NE + e];

    int i0 = 0;
#pragma unroll
    for (int e = 1; e < NE; e++) if (l[e] > l[i0]) i0 = e;
    int i1 = -1; float best = -1e30f;
#pragma unroll
    for (int e = 0; e < NE; e++)
        if (e != i0 && l[e] > best) { best = l[e]; i1 = e; }

    float w0 = 1.0f / (1.0f + expf(l[i1] - l[i0]));  // p0/(p0+p1)
    float w1 = 1.0f - w0;

    int s0 = atomicAdd(&g_cnt[i0], 1);
    g_tok[i0 * NT + s0] = t;
    g_wgt[i0 * NT + s0] = w0;
    int s1 = atomicAdd(&g_cnt[i1], 1);
    g_tok[i1 * NT + s1] = t;
    g_wgt[i1 * NT + s1] = w1;
}

// ---------------------------------------------------------------------------
// Grouped tf32 tensor-core GEMM (mma.sync m16n8k8), 128x128x16 CTA tile,
// 4 warps, warp tile 64x64, cp.async double-buffered.
//   SECOND=false: H[e,m,:] = silu( x[tok[e,m],:] @ W1[e] )     (K=1024, N=2048)
//   SECOND=true : out[tok[e,m],:] += wgt[e,m] * (H[e,m,:] @ W2[e])  (K=2048, N=1024)
// ---------------------------------------------------------------------------
#define BM 128
#define BN 128
#define BK 16
#define ASTR 20      // A smem row stride (floats): banks (4m+k) conflict-free
#define BSTR 136     // B smem row stride (floats): banks (8k+n) conflict-free

template<int KTOT, int LDB, bool SECOND>
__global__ __launch_bounds__(128)
void k_gemm_mma(const float* __restrict__ Aglob,
                const float* __restrict__ Bglob,
                float* __restrict__ outp)
{
    const int e   = blockIdx.z;
    const int cnt = g_cnt[e];
    const int m0  = blockIdx.x * BM;
    if (m0 >= cnt) return;
    const int n0  = blockIdx.y * BN;

    __shared__ float As[2][BM * ASTR];  // [m][k] padded
    __shared__ float Bs[2][BK * BSTR];  // [k][n] padded

    const int tid  = threadIdx.x;
    const int wid  = tid >> 5;
    const int lane = tid & 31;
    const int wm   = wid >> 1;      // 0..1
    const int wn   = wid & 1;       // 0..1
    const int gp   = lane >> 2;     // 0..7
    const int tig  = lane & 3;      // 0..3

    // ---- loader setup: this thread owns A row (m0+tid) ----
    const int  arow_l = m0 + tid;
    const bool avalid = arow_l < cnt;
    const float* Aptr;
    if (SECOND) {
        Aptr = &g_h[(size_t)e * NT * NF] + (size_t)arow_l * NF;
    } else {
        int token = avalid ? g_tok[e * NT + arow_l] : 0;
        Aptr = Aglob + (size_t)token * ND;
    }
    const float* Bexp = Bglob + (size_t)e * KTOT * LDB + n0;
    const int asz = avalid ? 16 : 0;   // src-size 0 -> zfill for ragged rows

    const uint32_t sA = (uint32_t)__cvta_generic_to_shared(&As[0][0]);
    const uint32_t sB = (uint32_t)__cvta_generic_to_shared(&Bs[0][0]);
    const uint32_t ABUF = BM * ASTR * 4;
    const uint32_t BBUF = BK * BSTR * 4;

    float acc[4][8][4];
#pragma unroll
    for (int i = 0; i < 4; i++)
#pragma unroll
        for (int j = 0; j < 8; j++)
#pragma unroll
            for (int c = 0; c < 4; c++) acc[i][j][c] = 0.0f;

    const int KT = KTOT / BK;

    // prologue: load tile 0 into buf 0
    {
        uint32_t sa = sA + (uint32_t)tid * (ASTR * 4);
        const float* ga = Aptr;
#pragma unroll
        for (int c = 0; c < 4; c++)
            asm volatile("cp.async.cg.shared.global [%0], [%1], 16, %2;"
                         :: "r"(sa + c * 16), "l"(ga + c * 4), "r"(asz));
#pragma unroll
        for (int it = 0; it < 4; it++) {
            int id = tid + it * 128;
            int br = id >> 5, bc = (id & 31) * 4;
            uint32_t sb = sB + (uint32_t)(br * BSTR + bc) * 4;
            const float* gb = Bexp + (size_t)br * LDB + bc;
            asm volatile("cp.async.cg.shared.global [%0], [%1], 16;"
                         :: "r"(sb), "l"(gb));
        }
        asm volatile("cp.async.commit_group;");
    }

    for (int kt = 0; kt < KT; kt++) {
        if (kt + 1 < KT) {
            // async-load next tile into the other buffer
            int buf = (kt + 1) & 1;
            int k0  = (kt + 1) * BK;
            uint32_t sa = sA + (uint32_t)buf * ABUF + (uint32_t)tid * (ASTR * 4);
            const float* ga = Aptr + k0;
#pragma unroll
            for (int c = 0; c < 4; c++)
                asm volatile("cp.async.cg.shared.global [%0], [%1], 16, %2;"
                             :: "r"(sa + c * 16), "l"(ga + c * 4), "r"(asz));
#pragma unroll
            for (int it = 0; it < 4; it++) {
                int id = tid + it * 128;
                int br = id >> 5, bc = (id & 31) * 4;
                uint32_t sb = sB + (uint32_t)buf * BBUF + (uint32_t)(br * BSTR + bc) * 4;
                const float* gb = Bexp + (size_t)(k0 + br) * LDB + bc;
                asm volatile("cp.async.cg.shared.global [%0], [%1], 16;"
                             :: "r"(sb), "l"(gb));
            }
            asm volatile("cp.async.commit_group;");
            asm volatile("cp.async.wait_group 1;");
        } else {
            asm volatile("cp.async.wait_group 0;");
        }
        __syncthreads();

        const int buf = kt & 1;
        const float* Ab = &As[buf][(wm * 64 + gp) * ASTR + tig];
        const float* Bb = &Bs[buf][tig * BSTR + wn * 64 + gp];

#pragma unroll
        for (int ks = 0; ks < 2; ks++) {
            uint32_t af[4][4];
#pragma unroll
            for (int fi = 0; fi < 4; fi++) {
                float v0 = Ab[(fi * 16 + 0) * ASTR + ks * 8 + 0];
                float v1 = Ab[(fi * 16 + 8) * ASTR + ks * 8 + 0];
                float v2 = Ab[(fi * 16 + 0) * ASTR + ks * 8 + 4];
                float v3 = Ab[(fi * 16 + 8) * ASTR + ks * 8 + 4];
                asm("cvt.rna.tf32.f32 %0, %1;" : "=r"(af[fi][0]) : "f"(v0));
                asm("cvt.rna.tf32.f32 %0, %1;" : "=r"(af[fi][1]) : "f"(v1));
                asm("cvt.rna.tf32.f32 %0, %1;" : "=r"(af[fi][2]) : "f"(v2));
                asm("cvt.rna.tf32.f32 %0, %1;" : "=r"(af[fi][3]) : "f"(v3));
            }
            uint32_t bf[8][2];
#pragma unroll
            for (int fj = 0; fj < 8; fj++) {
                float w0 = Bb[(ks * 8 + 0) * BSTR + fj * 8];
                float w1 = Bb[(ks * 8 + 4) * BSTR + fj * 8];
                asm("cvt.rna.tf32.f32 %0, %1;" : "=r"(bf[fj][0]) : "f"(w0));
                asm("cvt.rna.tf32.f32 %0, %1;" : "=r"(bf[fj][1]) : "f"(w1));
            }
#pragma unroll
            for (int fi = 0; fi < 4; fi++)
#pragma unroll
                for (int fj = 0; fj < 8; fj++)
                    asm volatile(
                        "mma.sync.aligned.m16n8k8.row.col.f32.tf32.tf32.f32 "
                        "{%0,%1,%2,%3}, {%4,%5,%6,%7}, {%8,%9}, {%0,%1,%2,%3};"
                        : "+f"(acc[fi][fj][0]), "+f"(acc[fi][fj][1]),
                          "+f"(acc[fi][fj][2]), "+f"(acc[fi][fj][3])
                        : "r"(af[fi][0]), "r"(af[fi][1]), "r"(af[fi][2]), "r"(af[fi][3]),
                          "r"(bf[fj][0]), "r"(bf[fj][1]));
        }
        __syncthreads();
    }

    // ---- epilogue ----
    if (!SECOND) {
        float* H = &g_h[(size_t)e * NT * NF];
#pragma unroll
        for (int fi = 0; fi < 4; fi++) {
#pragma unroll
            for (int hh = 0; hh < 2; hh++) {
                int row = m0 + wm * 64 + fi * 16 + hh * 8 + gp;
                if (row < cnt) {
#pragma unroll
                    for (int fj = 0; fj < 8; fj++) {
                        int col = n0 + wn * 64 + fj * 8 + 2 * tig;
                        float v0 = acc[fi][fj][2 * hh + 0];
                        float v1 = acc[fi][fj][2 * hh + 1];
                        float2 s;
                        s.x = v0 / (1.0f + expf(-v0));
                        s.y = v1 / (1.0f + expf(-v1));
                        *reinterpret_cast<float2*>(&H[(size_t)row * NF + col]) = s;
                    }
                }
            }
        }
    } else {
#pragma unroll
        for (int fi = 0; fi < 4; fi++) {
#pragma unroll
            for (int hh = 0; hh < 2; hh++) {
                int row = m0 + wm * 64 + fi * 16 + hh * 8 + gp;
                if (row < cnt) {
                    float w = g_wgt[e * NT + row];
                    int   t = g_tok[e * NT + row];
#pragma unroll
                    for (int fj = 0; fj < 8; fj++) {
                        int col = n0 + wn * 64 + fj * 8 + 2 * tig;
                        atomicAdd(&outp[(size_t)t * ND + col + 0], w * acc[fi][fj][2 * hh + 0]);
                        atomicAdd(&outp[(size_t)t * ND + col + 1], w * acc[fi][fj][2 * hh + 1]);
                    }
                }
            }
        }
    }
}

// ---------------------------------------------------------------------------
// launch
// ---------------------------------------------------------------------------
extern "C" void kernel_launch(void* const* d_in, const int* in_sizes, int n_in,
                              void* d_out, int out_size) {
    const float* hidden = (const float*)d_in[0];   // [T, D]
    const float* logits = (const float*)d_in[1];   // [T, E]
    const float* W1     = (const float*)d_in[2];   // [E, D, F]
    const float* W2     = (const float*)d_in[3];   // [E, F, D]
    float* out = (float*)d_out;                    // [T, D]

    k_zero<<<(NT * ND / 4 + 255) / 256, 256>>>((float4*)out);
    k_router<<<(NT + 255) / 256, 256>>>(logits);

    dim3 g1(NT / BM, NF / BN, NE);   // (16, 16, 8); ragged blocks exit early
    k_gemm_mma<ND, NF, false><<<g1, 128>>>(hidden, W1, nullptr);

    dim3 g2(NT / BM, ND / BN, NE);   // (16, 8, 8)
    k_gemm_mma<NF, ND, true><<<g2, 128>>>(hidden, W2, out);
}

// round 5
// speedup vs baseline: 4.0557x; 1.6924x over previous
#include <cuda_runtime.h>
#include <math.h>
#include <stdint.h>

// Problem dims (fixed by the dataset)
#define NT 2048      // tokens (B*S)
#define NE 8         // experts
#define ND 1024      // d_model
#define NF 2048      // d_ff

// -------- scratch (alloc-free: __device__ globals) --------
__device__ int   g_cnt[NE];
__device__ int   g_tok[NE * NT];
__device__ float g_wgt[NE * NT];
__device__ float g_h[(size_t)NE * NT * NF];   // silu(x@W1), slot-major per expert

// ---------------------------------------------------------------------------
// Kernel 0: zero output + expert counters
// ---------------------------------------------------------------------------
__global__ void k_zero(float4* __restrict__ out) {
    int i = blockIdx.x * blockDim.x + threadIdx.x;
    if (i < NT * ND / 4) out[i] = make_float4(0.f, 0.f, 0.f, 0.f);
    if (i < NE) g_cnt[i] = 0;
}

// ---------------------------------------------------------------------------
// Kernel 1: router — softmax over 8 logits, top-2, renormalize, dispatch
// ---------------------------------------------------------------------------
__global__ void k_router(const float* __restrict__ logits) {
    int t = blockIdx.x * blockDim.x + threadIdx.x;
    if (t >= NT) return;
    float l[NE];
#pragma unroll
    for (int e = 0; e < NE; e++) l[e] = logits[t * NE + e];

    int i0 = 0;
#pragma unroll
    for (int e = 1; e < NE; e++) if (l[e] > l[i0]) i0 = e;
    int i1 = -1; float best = -1e30f;
#pragma unroll
    for (int e = 0; e < NE; e++)
        if (e != i0 && l[e] > best) { best = l[e]; i1 = e; }

    float w0 = 1.0f / (1.0f + expf(l[i1] - l[i0]));  // p0/(p0+p1)
    float w1 = 1.0f - w0;

    int s0 = atomicAdd(&g_cnt[i0], 1);
    g_tok[i0 * NT + s0] = t;
    g_wgt[i0 * NT + s0] = w0;
    int s1 = atomicAdd(&g_cnt[i1], 1);
    g_tok[i1 * NT + s1] = t;
    g_wgt[i1 * NT + s1] = w1;
}

// ---------------------------------------------------------------------------
// Grouped tf32 tensor-core GEMM (mma.sync m16n8k8), 128x128x16 CTA tile,
// 8 warps (256 threads), warp tile 32x64, cp.async double-buffered.
//   SECOND=false: H[e,m,:] = silu( x[tok[e,m],:] @ W1[e] )       (K=1024, N=2048)
//   SECOND=true : out[tok[e,m],:] += wgt[e,m] * (H[e,m,:] @ W2[e]) (K=2048, N=1024)
// ---------------------------------------------------------------------------
#define BM 128
#define BN 128
#define BK 16
#define ASTR 20      // A smem row stride (floats): banks (4m+k) conflict-free
#define BSTR 136     // B smem row stride (floats): banks (8k+n) conflict-free

template<int KTOT, int LDB, bool SECOND>
__global__ __launch_bounds__(256, 2)
void k_gemm_mma(const float* __restrict__ Aglob,
                const float* __restrict__ Bglob,
                float* __restrict__ outp)
{
    const int e   = blockIdx.z;
    const int cnt = g_cnt[e];
    const int m0  = blockIdx.x * BM;
    if (m0 >= cnt) return;
    const int n0  = blockIdx.y * BN;

    __shared__ float As[2][BM * ASTR];  // [m][k] padded
    __shared__ float Bs[2][BK * BSTR];  // [k][n] padded

    const int tid  = threadIdx.x;
    const int wid  = tid >> 5;
    const int lane = tid & 31;
    const int wm   = wid >> 1;      // 0..3  (m quarter, 32 rows)
    const int wn   = wid & 1;       // 0..1  (n half, 64 cols)
    const int gp   = lane >> 2;     // 0..7
    const int tig  = lane & 3;      // 0..3

    // ---- loader setup: thread owns A rows (tid>>2) and 64+(tid>>2) --------
    const int r0 = tid >> 2;              // 0..63
    const int c4 = (tid & 3) * 4;         // float offset within row
    const float* Aptr0;
    const float* Aptr1;
    int sz0, sz1;
    {
        int ra = m0 + r0, rb = m0 + 64 + r0;
        if (SECOND) {
            const float* Hbase = &g_h[(size_t)e * NT * NF];
            Aptr0 = Hbase + (size_t)ra * NF;
            Aptr1 = Hbase + (size_t)rb * NF;
        } else {
            int ta = (ra < cnt) ? g_tok[e * NT + ra] : 0;
            int tb = (rb < cnt) ? g_tok[e * NT + rb] : 0;
            Aptr0 = Aglob + (size_t)ta * ND;
            Aptr1 = Aglob + (size_t)tb * ND;
        }
        sz0 = (ra < cnt) ? 16 : 0;        // cp.async src-size 0 -> zfill
        sz1 = (rb < cnt) ? 16 : 0;
    }
    const float* Bexp = Bglob + (size_t)e * KTOT * LDB + n0;

    const uint32_t sA = (uint32_t)__cvta_generic_to_shared(&As[0][0]);
    const uint32_t sB = (uint32_t)__cvta_generic_to_shared(&Bs[0][0]);
    const uint32_t ABUF = BM * ASTR * 4;
    const uint32_t BBUF = BK * BSTR * 4;

    float acc[2][8][4];
#pragma unroll
    for (int i = 0; i < 2; i++)
#pragma unroll
        for (int j = 0; j < 8; j++)
#pragma unroll
            for (int c = 0; c < 4; c++) acc[i][j][c] = 0.0f;

    const int KT = KTOT / BK;

    // prologue: load tile 0 into buf 0
    {
        uint32_t saA0 = sA + (uint32_t)(r0 * ASTR + c4) * 4;
        uint32_t saA1 = sA + (uint32_t)((64 + r0) * ASTR + c4) * 4;
        asm volatile("cp.async.cg.shared.global [%0], [%1], 16, %2;"
                     :: "r"(saA0), "l"(Aptr0 + c4), "r"(sz0));
        asm volatile("cp.async.cg.shared.global [%0], [%1], 16, %2;"
                     :: "r"(saA1), "l"(Aptr1 + c4), "r"(sz1));
#pragma unroll
        for (int it = 0; it < 2; it++) {
            int id = tid + it * 256;
            int br = id >> 5, bc = (id & 31) * 4;
            uint32_t sbp = sB + (uint32_t)(br * BSTR + bc) * 4;
            asm volatile("cp.async.cg.shared.global [%0], [%1], 16;"
                         :: "r"(sbp), "l"(Bexp + (size_t)br * LDB + bc));
        }
        asm volatile("cp.async.commit_group;");
    }

    for (int kt = 0; kt < KT; kt++) {
        if (kt + 1 < KT) {
            int buf = (kt + 1) & 1;
            int k0  = (kt + 1) * BK;
            uint32_t saA0 = sA + buf * ABUF + (uint32_t)(r0 * ASTR + c4) * 4;
            uint32_t saA1 = sA + buf * ABUF + (uint32_t)((64 + r0) * ASTR + c4) * 4;
            asm volatile("cp.async.cg.shared.global [%0], [%1], 16, %2;"
                         :: "r"(saA0), "l"(Aptr0 + k0 + c4), "r"(sz0));
            asm volatile("cp.async.cg.shared.global [%0], [%1], 16, %2;"
                         :: "r"(saA1), "l"(Aptr1 + k0 + c4), "r"(sz1));
#pragma unroll
            for (int it = 0; it < 2; it++) {
                int id = tid + it * 256;
                int br = id >> 5, bc = (id & 31) * 4;
                uint32_t sbp = sB + buf * BBUF + (uint32_t)(br * BSTR + bc) * 4;
                asm volatile("cp.async.cg.shared.global [%0], [%1], 16;"
                             :: "r"(sbp), "l"(Bexp + (size_t)(k0 + br) * LDB + bc));
            }
            asm volatile("cp.async.commit_group;");
            asm volatile("cp.async.wait_group 1;");
        } else {
            asm volatile("cp.async.wait_group 0;");
        }
        __syncthreads();

        const int buf = kt & 1;
        const float* Ab = &As[buf][(wm * 32 + gp) * ASTR + tig];
        const float* Bb = &Bs[buf][tig * BSTR + wn * 64 + gp];

#pragma unroll
        for (int ks = 0; ks < 2; ks++) {
            uint32_t af[2][4];
#pragma unroll
            for (int fi = 0; fi < 2; fi++) {
                float v0 = Ab[(fi * 16 + 0) * ASTR + ks * 8 + 0];
                float v1 = Ab[(fi * 16 + 8) * ASTR + ks * 8 + 0];
                float v2 = Ab[(fi * 16 + 0) * ASTR + ks * 8 + 4];
                float v3 = Ab[(fi * 16 + 8) * ASTR + ks * 8 + 4];
                asm("cvt.rna.tf32.f32 %0, %1;" : "=r"(af[fi][0]) : "f"(v0));
                asm("cvt.rna.tf32.f32 %0, %1;" : "=r"(af[fi][1]) : "f"(v1));
                asm("cvt.rna.tf32.f32 %0, %1;" : "=r"(af[fi][2]) : "f"(v2));
                asm("cvt.rna.tf32.f32 %0, %1;" : "=r"(af[fi][3]) : "f"(v3));
            }
            uint32_t bf[8][2];
#pragma unroll
            for (int fj = 0; fj < 8; fj++) {
                float w0 = Bb[(ks * 8 + 0) * BSTR + fj * 8];
                float w1 = Bb[(ks * 8 + 4) * BSTR + fj * 8];
                asm("cvt.rna.tf32.f32 %0, %1;" : "=r"(bf[fj][0]) : "f"(w0));
                asm("cvt.rna.tf32.f32 %0, %1;" : "=r"(bf[fj][1]) : "f"(w1));
            }
#pragma unroll
            for (int fi = 0; fi < 2; fi++)
#pragma unroll
                for (int fj = 0; fj < 8; fj++)
                    asm volatile(
                        "mma.sync.aligned.m16n8k8.row.col.f32.tf32.tf32.f32 "
                        "{%0,%1,%2,%3}, {%4,%5,%6,%7}, {%8,%9}, {%0,%1,%2,%3};"
                        : "+f"(acc[fi][fj][0]), "+f"(acc[fi][fj][1]),
                          "+f"(acc[fi][fj][2]), "+f"(acc[fi][fj][3])
                        : "r"(af[fi][0]), "r"(af[fi][1]), "r"(af[fi][2]), "r"(af[fi][3]),
                          "r"(bf[fj][0]), "r"(bf[fj][1]));
        }
        __syncthreads();
    }

    // ---- epilogue ----
    if (!SECOND) {
        float* H = &g_h[(size_t)e * NT * NF];
#pragma unroll
        for (int fi = 0; fi < 2; fi++) {
#pragma unroll
            for (int hh = 0; hh < 2; hh++) {
                int row = m0 + wm * 32 + fi * 16 + hh * 8 + gp;
                if (row < cnt) {
#pragma unroll
                    for (int fj = 0; fj < 8; fj++) {
                        int col = n0 + wn * 64 + fj * 8 + 2 * tig;
                        float v0 = acc[fi][fj][2 * hh + 0];
                        float v1 = acc[fi][fj][2 * hh + 1];
                        float2 s;
                        s.x = v0 / (1.0f + expf(-v0));
                        s.y = v1 / (1.0f + expf(-v1));
                        *reinterpret_cast<float2*>(&H[(size_t)row * NF + col]) = s;
                    }
                }
            }
        }
    } else {
#pragma unroll
        for (int fi = 0; fi < 2; fi++) {
#pragma unroll
            for (int hh = 0; hh < 2; hh++) {
                int row = m0 + wm * 32 + fi * 16 + hh * 8 + gp;
                if (row < cnt) {
                    float w = g_wgt[e * NT + row];
                    int   t = g_tok[e * NT + row];
#pragma unroll
                    for (int fj = 0; fj < 8; fj++) {
                        int col = n0 + wn * 64 + fj * 8 + 2 * tig;
                        atomicAdd(&outp[(size_t)t * ND + col + 0], w * acc[fi][fj][2 * hh + 0]);
                        atomicAdd(&outp[(size_t)t * ND + col + 1], w * acc[fi][fj][2 * hh + 1]);
                    }
                }
            }
        }
    }
}

// ---------------------------------------------------------------------------
// launch
// ---------------------------------------------------------------------------
extern "C" void kernel_launch(void* const* d_in, const int* in_sizes, int n_in,
                              void* d_out, int out_size) {
    const float* hidden = (const float*)d_in[0];   // [T, D]
    const float* logits = (const float*)d_in[1];   // [T, E]
    const float* W1     = (const float*)d_in[2];   // [E, D, F]
    const float* W2     = (const float*)d_in[3];   // [E, F, D]
    float* out = (float*)d_out;                    // [T, D]

    k_zero<<<(NT * ND / 4 + 255) / 256, 256>>>((float4*)out);
    k_router<<<(NT + 255) / 256, 256>>>(logits);

    dim3 g1(NT / BM, NF / BN, NE);   // (16, 16, 8); ragged blocks exit early
    k_gemm_mma<ND, NF, false><<<g1, 256>>>(hidden, W1, nullptr);

    dim3 g2(NT / BM, ND / BN, NE);   // (16, 8, 8)
    k_gemm_mma<NF, ND, true><<<g2, 256>>>(hidden, W2, out);
}

// round 6
// speedup vs baseline: 7.3731x; 1.8180x over previous
#include <cuda_runtime.h>
#include <cuda_fp16.h>
#include <math.h>
#include <stdint.h>

// Problem dims (fixed by the dataset)
#define NT 2048      // tokens (B*S)
#define NE 8         // experts
#define ND 1024      // d_model
#define NF 2048      // d_ff

// -------- scratch (alloc-free: __device__ globals) --------
__device__ int   g_cnt[NE];
__device__ int   g_tok[NE * NT];
__device__ float g_wgt[NE * NT];
__device__ __align__(16) __half g_h[(size_t)NE * NT * NF];    // silu(x@W1), fp16
__device__ __align__(16) __half g_w1h[(size_t)NE * ND * NF];  // W1 in fp16
__device__ __align__(16) __half g_w2h[(size_t)NE * NF * ND];  // W2 in fp16
__device__ __align__(16) __half g_xh[NT * ND];                // hidden in fp16

// ---------------------------------------------------------------------------
// Kernel 0: zero output + expert counters
// ---------------------------------------------------------------------------
__global__ void k_zero(float4* __restrict__ out) {
    int i = blockIdx.x * blockDim.x + threadIdx.x;
    if (i < NT * ND / 4) out[i] = make_float4(0.f, 0.f, 0.f, 0.f);
    if (i < NE) g_cnt[i] = 0;
}

// ---------------------------------------------------------------------------
// Kernel 1: router — softmax over 8 logits, top-2, renormalize, dispatch
// ---------------------------------------------------------------------------
__global__ void k_router(const float* __restrict__ logits) {
    int t = blockIdx.x * blockDim.x + threadIdx.x;
    if (t >= NT) return;
    float l[NE];
#pragma unroll
    for (int e = 0; e < NE; e++) l[e] = logits[t * NE + e];

    int i0 = 0;
#pragma unroll
    for (int e = 1; e < NE; e++) if (l[e] > l[i0]) i0 = e;
    int i1 = -1; float best = -1e30f;
#pragma unroll
    for (int e = 0; e < NE; e++)
        if (e != i0 && l[e] > best) { best = l[e]; i1 = e; }

    float w0 = 1.0f / (1.0f + expf(l[i1] - l[i0]));
    float w1 = 1.0f - w0;

    int s0 = atomicAdd(&g_cnt[i0], 1);
    g_tok[i0 * NT + s0] = t;
    g_wgt[i0 * NT + s0] = w0;
    int s1 = atomicAdd(&g_cnt[i1], 1);
    g_tok[i1 * NT + s1] = t;
    g_wgt[i1 * NT + s1] = w1;
}

// ---------------------------------------------------------------------------
// fp32 -> fp16 conversion pass (round-to-nearest): W1, W2, hidden
// ---------------------------------------------------------------------------
union H2U { __half2 h; uint32_t u; };

__device__ __forceinline__ void cvt_store(const float4* __restrict__ src,
                                          uint2* __restrict__ dst, int i) {
    float4 v = src[i];
    H2U a, b;
    a.h = __floats2half2_rn(v.x, v.y);
    b.h = __floats2half2_rn(v.z, v.w);
    dst[i] = make_uint2(a.u, b.u);
}
__global__ void k_cvt_w1(const float4* __restrict__ src) {
    int i = blockIdx.x * blockDim.x + threadIdx.x;
    if (i < NE * ND * NF / 4) cvt_store(src, (uint2*)g_w1h, i);
}
__global__ void k_cvt_w2(const float4* __restrict__ src) {
    int i = blockIdx.x * blockDim.x + threadIdx.x;
    if (i < NE * NF * ND / 4) cvt_store(src, (uint2*)g_w2h, i);
}
__global__ void k_cvt_x(const float4* __restrict__ src) {
    int i = blockIdx.x * blockDim.x + threadIdx.x;
    if (i < NT * ND / 4) cvt_store(src, (uint2*)g_xh, i);
}

// ---------------------------------------------------------------------------
// fp16 tensor-core grouped GEMM: mma.sync m16n8k16, CTA tile 128x128, BK=32,
// 3-stage cp.async pipeline, ldmatrix fragment loads, XOR-swizzled SMEM.
//   SECOND=false: g_h = silu( gather(g_xh) @ g_w1h[e] )   (K=1024, N=2048)
//   SECOND=true : out += wgt * ( g_h @ g_w2h[e] )         (K=2048, N=1024)
// ---------------------------------------------------------------------------
#define BK  32
#define STG 16384    // per stage: 8KB A (128x32 half) + 8KB B (32x128 half)

#define LDSM4(r, a)                                                           \
    asm volatile("ldmatrix.sync.aligned.m8n8.x4.shared.b16 {%0,%1,%2,%3}, [%4];" \
                 : "=r"((r)[0]), "=r"((r)[1]), "=r"((r)[2]), "=r"((r)[3])     \
                 : "r"(a))
#define LDSM4T(r, a)                                                          \
    asm volatile("ldmatrix.sync.aligned.m8n8.x4.trans.shared.b16 {%0,%1,%2,%3}, [%4];" \
                 : "=r"((r)[0]), "=r"((r)[1]), "=r"((r)[2]), "=r"((r)[3])     \
                 : "r"(a))
#define MMA16816(c, a, b0v, b1v)                                              \
    asm volatile("mma.sync.aligned.m16n8k16.row.col.f32.f16.f16.f32 "         \
                 "{%0,%1,%2,%3},{%4,%5,%6,%7},{%8,%9},{%0,%1,%2,%3};"         \
                 : "+f"((c)[0]), "+f"((c)[1]), "+f"((c)[2]), "+f"((c)[3])     \
                 : "r"((a)[0]), "r"((a)[1]), "r"((a)[2]), "r"((a)[3]),        \
                   "r"(b0v), "r"(b1v))

// SMEM layout (stage-relative byte offsets; all 16B chunks, swizzled):
//   A(m 0..127, kc 0..3):  (m>>1)*128 + ((((m&1)<<2)|kc) ^ ((m>>1)&7))*16
//   B(k 0..31,  n8 0..15): 8192 + k*256 + ((n8 ^ (k&7)))*16
__device__ __forceinline__ uint32_t a_off(int m, int kc) {
    return (uint32_t)((m >> 1) * 128 + (((((m & 1) << 2) | kc) ^ ((m >> 1) & 7)) * 16));
}
__device__ __forceinline__ uint32_t b_off(int k, int n8) {
    return (uint32_t)(8192 + k * 256 + ((n8 ^ (k & 7)) * 16));
}

template<int KTOT, int LDB, bool SECOND>
__global__ __launch_bounds__(256, 2)
void k_gemm_h(const float* __restrict__ hidden_unused, float* __restrict__ outp)
{
    const int e   = blockIdx.z;
    const int cnt = g_cnt[e];
    const int m0  = blockIdx.x * 128;
    if (m0 >= cnt) return;
    const int n0  = blockIdx.y * 128;

    __shared__ __align__(128) char smem[3 * STG];
    const uint32_t sb = (uint32_t)__cvta_generic_to_shared(smem);

    const int tid  = threadIdx.x;
    const int wid  = tid >> 5;
    const int lane = tid & 31;
    const int wm   = wid >> 1;      // 0..3  m quarter (32 rows)
    const int wn   = wid & 1;       // 0..1  n half (64 cols)
    const int gp   = lane >> 2;     // 0..7
    const int tig  = lane & 3;      // 0..3

    // ---- loader state (each thread: 2 A chunks + 2 B chunks of 16B) -------
    const int kc  = tid & 3;          // A k-chunk (8 halves)
    const int mA  = tid >> 2;         // A row 0..63 (and +64)
    const int n8  = tid & 15;         // B n-chunk
    const int kB  = tid >> 4;         // B k-row 0..15 (and +16)

    const __half* ap0; const __half* ap1;
    int sz0, sz1;
    {
        int ra = m0 + mA, rb = ra + 64;
        if (SECOND) {
            ap0 = g_h + ((size_t)e * NT + ra) * NF + kc * 8;
            ap1 = g_h + ((size_t)e * NT + rb) * NF + kc * 8;
        } else {
            int ta = (ra < cnt) ? g_tok[e * NT + ra] : 0;
            int tb = (rb < cnt) ? g_tok[e * NT + rb] : 0;
            ap0 = g_xh + (size_t)ta * ND + kc * 8;
            ap1 = g_xh + (size_t)tb * ND + kc * 8;
        }
        sz0 = (ra < cnt) ? 16 : 0;
        sz1 = (rb < cnt) ? 16 : 0;
    }
    const __half* Bh  = SECOND ? g_w2h : g_w1h;
    const __half* bp0 = Bh + (size_t)e * KTOT * LDB + n0 + (size_t)kB * LDB + n8 * 8;
    const __half* bp1 = bp0 + (size_t)16 * LDB;

    const uint32_t ad0 = a_off(mA, kc);
    const uint32_t ad1 = a_off(mA + 64, kc);
    const uint32_t bd0 = b_off(kB, n8);
    const uint32_t bd1 = bd0 + 4096;              // (k+16)&7 == k&7

    // ---- fragment smem offsets (stage-relative), precomputed --------------
    const int lf = lane & 15, lh = lane >> 4;
    uint32_t aoff[2][2];  // [fi][ks]
#pragma unroll
    for (int fi = 0; fi < 2; fi++)
#pragma unroll
        for (int ks = 0; ks < 2; ks++)
            aoff[fi][ks] = a_off(wm * 32 + fi * 16 + lf, ks * 2 + lh);
    uint32_t boff[2][4];  // [ks][fjp]
#pragma unroll
    for (int ks = 0; ks < 2; ks++)
#pragma unroll
        for (int fjp = 0; fjp < 4; fjp++)
            boff[ks][fjp] = b_off(ks * 16 + lf, wn * 8 + fjp * 2 + lh);

    float acc[2][8][4];
#pragma unroll
    for (int i = 0; i < 2; i++)
#pragma unroll
        for (int j = 0; j < 8; j++)
#pragma unroll
            for (int c = 0; c < 4; c++) acc[i][j][c] = 0.0f;

    const int KT = KTOT / BK;

    // ---- stage loader ------------------------------------------------------
    auto load_stage = [&](int s, int kt) {
        const uint32_t base = sb + (uint32_t)s * STG;
        const int k0 = kt * BK;                     // halves
        asm volatile("cp.async.cg.shared.global [%0], [%1], 16, %2;"
                     :: "r"(base + ad0), "l"(ap0 + k0), "r"(sz0));
        asm volatile("cp.async.cg.shared.global [%0], [%1], 16, %2;"
                     :: "r"(base + ad1), "l"(ap1 + k0), "r"(sz1));
        asm volatile("cp.async.cg.shared.global [%0], [%1], 16;"
                     :: "r"(base + bd0), "l"(bp0 + (size_t)k0 * LDB));
        asm volatile("cp.async.cg.shared.global [%0], [%1], 16;"
                     :: "r"(base + bd1), "l"(bp1 + (size_t)k0 * LDB));
    };

    load_stage(0, 0);
    asm volatile("cp.async.commit_group;");
    load_stage(1, 1);
    asm volatile("cp.async.commit_group;");

    int s = 0, s2 = 2;
    for (int kt = 0; kt < KT; kt++) {
        asm volatile("cp.async.wait_group 1;");
        __syncthreads();

        if (kt + 2 < KT) load_stage(s2, kt + 2);
        asm volatile("cp.async.commit_group;");

        const uint32_t base = sb + (uint32_t)s * STG;
#pragma unroll
        for (int ks = 0; ks < 2; ks++) {
            uint32_t A0[4], A1[4];
            LDSM4(A0, base + aoff[0][ks]);
            LDSM4(A1, base + aoff[1][ks]);
            uint32_t Bf[8][2];
#pragma unroll
            for (int fjp = 0; fjp < 4; fjp++) {
                uint32_t r[4];
                LDSM4T(r, base + boff[ks][fjp]);
                Bf[fjp * 2 + 0][0] = r[0];  Bf[fjp * 2 + 0][1] = r[1];
                Bf[fjp * 2 + 1][0] = r[2];  Bf[fjp * 2 + 1][1] = r[3];
            }
#pragma unroll
            for (int fj = 0; fj < 8; fj++) {
                MMA16816(acc[0][fj], A0, Bf[fj][0], Bf[fj][1]);
                MMA16816(acc[1][fj], A1, Bf[fj][0], Bf[fj][1]);
            }
        }
        s  = (s  == 2) ? 0 : s  + 1;
        s2 = (s2 == 2) ? 0 : s2 + 1;
    }

    // ---- epilogue ----------------------------------------------------------
    if (!SECOND) {
#pragma unroll
        for (int fi = 0; fi < 2; fi++) {
#pragma unroll
            for (int hh = 0; hh < 2; hh++) {
                int row = m0 + wm * 32 + fi * 16 + hh * 8 + gp;
                if (row < cnt) {
                    __half* Hrow = g_h + ((size_t)e * NT + row) * NF;
#pragma unroll
                    for (int fj = 0; fj < 8; fj++) {
                        int col = n0 + wn * 64 + fj * 8 + 2 * tig;
                        float v0 = acc[fi][fj][2 * hh + 0];
                        float v1 = acc[fi][fj][2 * hh + 1];
                        float s0v = v0 / (1.0f + expf(-v0));
                        float s1v = v1 / (1.0f + expf(-v1));
                        *reinterpret_cast<__half2*>(Hrow + col) =
                            __floats2half2_rn(s0v, s1v);
                    }
                }
            }
        }
    } else {
#pragma unroll
        for (int fi = 0; fi < 2; fi++) {
#pragma unroll
            for (int hh = 0; hh < 2; hh++) {
                int row = m0 + wm * 32 + fi * 16 + hh * 8 + gp;
                if (row < cnt) {
                    float w = g_wgt[e * NT + row];
                    int   t = g_tok[e * NT + row];
                    float* orow = outp + (size_t)t * ND;
#pragma unroll
                    for (int fj = 0; fj < 8; fj++) {
                        int col = n0 + wn * 64 + fj * 8 + 2 * tig;
                        atomicAdd(orow + col + 0, w * acc[fi][fj][2 * hh + 0]);
                        atomicAdd(orow + col + 1, w * acc[fi][fj][2 * hh + 1]);
                    }
                }
            }
        }
    }
}

// ---------------------------------------------------------------------------
// launch
// ---------------------------------------------------------------------------
extern "C" void kernel_launch(void* const* d_in, const int* in_sizes, int n_in,
                              void* d_out, int out_size) {
    const float* hidden = (const float*)d_in[0];   // [T, D]
    const float* logits = (const float*)d_in[1];   // [T, E]
    const float* W1     = (const float*)d_in[2];   // [E, D, F]
    const float* W2     = (const float*)d_in[3];   // [E, F, D]
    float* out = (float*)d_out;                    // [T, D]

    k_zero<<<(NT * ND / 4 + 255) / 256, 256>>>((float4*)out);
    k_router<<<(NT + 255) / 256, 256>>>(logits);

    k_cvt_w1<<<NE * ND * NF / 4 / 256, 256>>>((const float4*)W1);
    k_cvt_w2<<<NE * NF * ND / 4 / 256, 256>>>((const float4*)W2);
    k_cvt_x <<<NT * ND / 4 / 256, 256>>>((const float4*)hidden);

    dim3 g1(NT / 128, NF / 128, NE);   // (16, 16, 8); ragged blocks exit early
    k_gemm_h<ND, NF, false><<<g1, 256>>>(hidden, nullptr);

    dim3 g2(NT / 128, ND / 128, NE);   // (16, 8, 8)
    k_gemm_h<NF, ND, true><<<g2, 256>>>(hidden, out);
}

// round 7
// speedup vs baseline: 8.0213x; 1.0879x over previous
#include <cuda_runtime.h>
#include <cuda_fp16.h>
#include <math.h>
#include <stdint.h>

// Problem dims (fixed by the dataset)
#define NT 2048      // tokens (B*S)
#define NE 8         // experts
#define ND 1024      // d_model
#define NF 2048      // d_ff

// -------- scratch (alloc-free: __device__ globals) --------
__device__ int   g_cnt[NE];
__device__ int   g_tok[NE * NT];
__device__ float g_wgt[NE * NT];
__device__ __align__(16) __half g_h[(size_t)NE * NT * NF];    // silu(x@W1), fp16
__device__ __align__(16) __half g_w1h[(size_t)NE * ND * NF];  // W1 in fp16
__device__ __align__(16) __half g_w2h[(size_t)NE * NF * ND];  // W2 in fp16
__device__ __align__(16) __half g_xh[NT * ND];                // hidden in fp16

// ---------------------------------------------------------------------------
// fp32 -> fp16 helpers
// ---------------------------------------------------------------------------
union H2U { __half2 h; uint32_t u; };

__device__ __forceinline__ void cvt_store(const float4* __restrict__ src,
                                          uint2* __restrict__ dst, size_t i) {
    float4 v = src[i];
    H2U a, b;
    a.h = __floats2half2_rn(v.x, v.y);
    b.h = __floats2half2_rn(v.z, v.w);
    dst[i] = make_uint2(a.u, b.u);
}

// ---------------------------------------------------------------------------
// Kernel 0: prep — zero output, convert hidden to fp16, zero counters
// ---------------------------------------------------------------------------
__global__ void k_prep(float4* __restrict__ out, const float4* __restrict__ x) {
    int i = blockIdx.x * blockDim.x + threadIdx.x;
    if (i < NT * ND / 4) {
        out[i] = make_float4(0.f, 0.f, 0.f, 0.f);
        cvt_store(x, (uint2*)g_xh, (size_t)i);
    }
    if (i < NE) g_cnt[i] = 0;
}

// ---------------------------------------------------------------------------
// Kernel 1: router — softmax over 8 logits, top-2, renormalize, dispatch
// ---------------------------------------------------------------------------
__global__ void k_router(const float* __restrict__ logits) {
    int t = blockIdx.x * blockDim.x + threadIdx.x;
    if (t >= NT) return;
    float l[NE];
#pragma unroll
    for (int e = 0; e < NE; e++) l[e] = logits[t * NE + e];

    int i0 = 0;
#pragma unroll
    for (int e = 1; e < NE; e++) if (l[e] > l[i0]) i0 = e;
    int i1 = -1; float best = -1e30f;
#pragma unroll
    for (int e = 0; e < NE; e++)
        if (e != i0 && l[e] > best) { best = l[e]; i1 = e; }

    float w0 = 1.0f / (1.0f + expf(l[i1] - l[i0]));
    float w1 = 1.0f - w0;

    int s0 = atomicAdd(&g_cnt[i0], 1);
    g_tok[i0 * NT + s0] = t;
    g_wgt[i0 * NT + s0] = w0;
    int s1 = atomicAdd(&g_cnt[i1], 1);
    g_tok[i1 * NT + s1] = t;
    g_wgt[i1 * NT + s1] = w1;
}

// ---------------------------------------------------------------------------
// Kernel 2: convert W1 (must finish before GEMM1)
// ---------------------------------------------------------------------------
__global__ void k_cvt_w1(const float4* __restrict__ src) {
    int i = blockIdx.x * blockDim.x + threadIdx.x;
    if (i < NE * ND * NF / 4) cvt_store(src, (uint2*)g_w1h, (size_t)i);
}

// ---------------------------------------------------------------------------
// fp16 tensor-core grouped GEMM: mma.sync m16n8k16, CTA tile 128x128, BK=32,
// 4-stage cp.async pipeline (dynamic smem), ldmatrix, XOR-swizzled SMEM.
//   SECOND=false: g_h = silu( gather(g_xh) @ g_w1h[e] )   (K=1024, N=2048)
//                 + extra grid.z slices convert W2 fp32->fp16 concurrently
//   SECOND=true : out += wgt * ( g_h @ g_w2h[e] )         (K=2048, N=1024)
// ---------------------------------------------------------------------------
#define BK  32
#define STG 16384    // per stage: 8KB A (128x32 half) + 8KB B (32x128 half)
#define NSTAGE 4
#define DSMEM (NSTAGE * STG)

#define LDSM4(r, a)                                                           \
    asm volatile("ldmatrix.sync.aligned.m8n8.x4.shared.b16 {%0,%1,%2,%3}, [%4];" \
                 : "=r"((r)[0]), "=r"((r)[1]), "=r"((r)[2]), "=r"((r)[3])     \
                 : "r"(a))
#define LDSM4T(r, a)                                                          \
    asm volatile("ldmatrix.sync.aligned.m8n8.x4.trans.shared.b16 {%0,%1,%2,%3}, [%4];" \
                 : "=r"((r)[0]), "=r"((r)[1]), "=r"((r)[2]), "=r"((r)[3])     \
                 : "r"(a))
#define MMA16816(c, a, b0v, b1v)                                              \
    asm volatile("mma.sync.aligned.m16n8k16.row.col.f32.f16.f16.f32 "         \
                 "{%0,%1,%2,%3},{%4,%5,%6,%7},{%8,%9},{%0,%1,%2,%3};"         \
                 : "+f"((c)[0]), "+f"((c)[1]), "+f"((c)[2]), "+f"((c)[3])     \
                 : "r"((a)[0]), "r"((a)[1]), "r"((a)[2]), "r"((a)[3]),        \
                   "r"(b0v), "r"(b1v))

// SMEM layout (stage-relative byte offsets; 16B chunks, XOR-swizzled):
//   A(m 0..127, kc 0..3):  (m>>1)*128 + ((((m&1)<<2)|kc) ^ ((m>>1)&7))*16
//   B(k 0..31,  n8 0..15): 8192 + k*256 + ((n8 ^ (k&7)))*16
__device__ __forceinline__ uint32_t a_off(int m, int kc) {
    return (uint32_t)((m >> 1) * 128 + (((((m & 1) << 2) | kc) ^ ((m >> 1) & 7)) * 16));
}
__device__ __forceinline__ uint32_t b_off(int k, int n8) {
    return (uint32_t)(8192 + k * 256 + ((n8 ^ (k & 7)) * 16));
}

template<int KTOT, int LDB, bool SECOND>
__global__ __launch_bounds__(256, 2)
void k_gemm_h(const float4* __restrict__ w2src, float* __restrict__ outp)
{
    // ---- piggy-backed W2 conversion CTAs (GEMM1 launch only) --------------
    if (!SECOND && blockIdx.z >= NE) {
        const int slice = blockIdx.z - NE;                 // 0..7
        const int cta   = blockIdx.y * 16 + blockIdx.x;    // 0..255
        size_t base = (((size_t)slice * 256 + cta) * 8) * 256 + threadIdx.x;
        uint2* dst = (uint2*)g_w2h;
#pragma unroll
        for (int r = 0; r < 8; r++)
            cvt_store(w2src, dst, base + (size_t)r * 256); // total 8*256*256*8 = NE*NF*ND/4
        return;
    }

    const int e   = blockIdx.z;
    const int cnt = g_cnt[e];
    const int m0  = blockIdx.x * 128;
    if (m0 >= cnt) return;
    const int n0  = blockIdx.y * 128;

    extern __shared__ __align__(128) char smem[];
    const uint32_t sb = (uint32_t)__cvta_generic_to_shared(smem);

    const int tid  = threadIdx.x;
    const int wid  = tid >> 5;
    const int lane = tid & 31;
    const int wm   = wid >> 1;      // 0..3  m quarter (32 rows)
    const int wn   = wid & 1;       // 0..1  n half (64 cols)
    const int gp   = lane >> 2;     // 0..7
    const int tig  = lane & 3;      // 0..3

    // ---- loader state (each thread: 2 A chunks + 2 B chunks of 16B) -------
    const int kc  = tid & 3;          // A k-chunk (8 halves)
    const int mA  = tid >> 2;         // A row 0..63 (and +64)
    const int n8  = tid & 15;         // B n-chunk
    const int kB  = tid >> 4;         // B k-row 0..15 (and +16)

    const __half* ap0; const __half* ap1;
    int sz0, sz1;
    {
        int ra = m0 + mA, rb = ra + 64;
        if (SECOND) {
            ap0 = g_h + ((size_t)e * NT + ra) * NF + kc * 8;
            ap1 = g_h + ((size_t)e * NT + rb) * NF + kc * 8;
        } else {
            int ta = (ra < cnt) ? g_tok[e * NT + ra] : 0;
            int tb = (rb < cnt) ? g_tok[e * NT + rb] : 0;
            ap0 = g_xh + (size_t)ta * ND + kc * 8;
            ap1 = g_xh + (size_t)tb * ND + kc * 8;
        }
        sz0 = (ra < cnt) ? 16 : 0;
        sz1 = (rb < cnt) ? 16 : 0;
    }
    const __half* Bh  = SECOND ? g_w2h : g_w1h;
    const __half* bp0 = Bh + (size_t)e * KTOT * LDB + n0 + (size_t)kB * LDB + n8 * 8;
    const __half* bp1 = bp0 + (size_t)16 * LDB;

    const uint32_t ad0 = a_off(mA, kc);
    const uint32_t ad1 = a_off(mA + 64, kc);
    const uint32_t bd0 = b_off(kB, n8);
    const uint32_t bd1 = bd0 + 4096;              // (k+16)&7 == k&7

    // ---- fragment smem offsets (stage-relative), precomputed --------------
    const int lf = lane & 15, lh = lane >> 4;
    uint32_t aoff[2][2];  // [fi][ks]
#pragma unroll
    for (int fi = 0; fi < 2; fi++)
#pragma unroll
        for (int ks = 0; ks < 2; ks++)
            aoff[fi][ks] = a_off(wm * 32 + fi * 16 + lf, ks * 2 + lh);
    uint32_t boff[2][4];  // [ks][fjp]
#pragma unroll
    for (int ks = 0; ks < 2; ks++)
#pragma unroll
        for (int fjp = 0; fjp < 4; fjp++)
            boff[ks][fjp] = b_off(ks * 16 + lf, wn * 8 + fjp * 2 + lh);

    float acc[2][8][4];
#pragma unroll
    for (int i = 0; i < 2; i++)
#pragma unroll
        for (int j = 0; j < 8; j++)
#pragma unroll
            for (int c = 0; c < 4; c++) acc[i][j][c] = 0.0f;

    const int KT = KTOT / BK;

    // ---- stage loader ------------------------------------------------------
    auto load_stage = [&](int s, int kt) {
        const uint32_t base = sb + (uint32_t)s * STG;
        const int k0 = kt * BK;                     // halves
        asm volatile("cp.async.cg.shared.global [%0], [%1], 16, %2;"
                     :: "r"(base + ad0), "l"(ap0 + k0), "r"(sz0));
        asm volatile("cp.async.cg.shared.global [%0], [%1], 16, %2;"
                     :: "r"(base + ad1), "l"(ap1 + k0), "r"(sz1));
        asm volatile("cp.async.cg.shared.global [%0], [%1], 16;"
                     :: "r"(base + bd0), "l"(bp0 + (size_t)k0 * LDB));
        asm volatile("cp.async.cg.shared.global [%0], [%1], 16;"
                     :: "r"(base + bd1), "l"(bp1 + (size_t)k0 * LDB));
    };

    load_stage(0, 0);
    asm volatile("cp.async.commit_group;");
    load_stage(1, 1);
    asm volatile("cp.async.commit_group;");
    load_stage(2, 2);
    asm volatile("cp.async.commit_group;");

    for (int kt = 0; kt < KT; kt++) {
        asm volatile("cp.async.wait_group 2;");
        __syncthreads();

        if (kt + 3 < KT) load_stage((kt + 3) & 3, kt + 3);
        asm volatile("cp.async.commit_group;");

        const uint32_t base = sb + (uint32_t)(kt & 3) * STG;
#pragma unroll
        for (int ks = 0; ks < 2; ks++) {
            uint32_t A0[4], A1[4];
            LDSM4(A0, base + aoff[0][ks]);
            LDSM4(A1, base + aoff[1][ks]);
            uint32_t Bf[8][2];
#pragma unroll
            for (int fjp = 0; fjp < 4; fjp++) {
                uint32_t r[4];
                LDSM4T(r, base + boff[ks][fjp]);
                Bf[fjp * 2 + 0][0] = r[0];  Bf[fjp * 2 + 0][1] = r[1];
                Bf[fjp * 2 + 1][0] = r[2];  Bf[fjp * 2 + 1][1] = r[3];
            }
#pragma unroll
            for (int fj = 0; fj < 8; fj++) {
                MMA16816(acc[0][fj], A0, Bf[fj][0], Bf[fj][1]);
                MMA16816(acc[1][fj], A1, Bf[fj][0], Bf[fj][1]);
            }
        }
    }

    // ---- epilogue ----------------------------------------------------------
    if (!SECOND) {
#pragma unroll
        for (int fi = 0; fi < 2; fi++) {
#pragma unroll
            for (int hh = 0; hh < 2; hh++) {
                int row = m0 + wm * 32 + fi * 16 + hh * 8 + gp;
                if (row < cnt) {
                    __half* Hrow = g_h + ((size_t)e * NT + row) * NF;
#pragma unroll
                    for (int fj = 0; fj < 8; fj++) {
                        int col = n0 + wn * 64 + fj * 8 + 2 * tig;
                        float v0 = acc[fi][fj][2 * hh + 0];
                        float v1 = acc[fi][fj][2 * hh + 1];
                        float s0v = v0 / (1.0f + expf(-v0));
                        float s1v = v1 / (1.0f + expf(-v1));
                        *reinterpret_cast<__half2*>(Hrow + col) =
                            __floats2half2_rn(s0v, s1v);
                    }
                }
            }
        }
    } else {
#pragma unroll
        for (int fi = 0; fi < 2; fi++) {
#pragma unroll
            for (int hh = 0; hh < 2; hh++) {
                int row = m0 + wm * 32 + fi * 16 + hh * 8 + gp;
                if (row < cnt) {
                    float w = g_wgt[e * NT + row];
                    int   t = g_tok[e * NT + row];
                    float* orow = outp + (size_t)t * ND;
#pragma unroll
                    for (int fj = 0; fj < 8; fj++) {
                        int col = n0 + wn * 64 + fj * 8 + 2 * tig;
                        atomicAdd(orow + col + 0, w * acc[fi][fj][2 * hh + 0]);
                        atomicAdd(orow + col + 1, w * acc[fi][fj][2 * hh + 1]);
                    }
                }
            }
        }
    }
}

// ---------------------------------------------------------------------------
// launch
// ---------------------------------------------------------------------------
extern "C" void kernel_launch(void* const* d_in, const int* in_sizes, int n_in,
                              void* d_out, int out_size) {
    const float* hidden = (const float*)d_in[0];   // [T, D]
    const float* logits = (const float*)d_in[1];   // [T, E]
    const float* W1     = (const float*)d_in[2];   // [E, D, F]
    const float* W2     = (const float*)d_in[3];   // [E, F, D]
    float* out = (float*)d_out;                    // [T, D]

    static int smem_set = 0;
    if (!smem_set) {
        cudaFuncSetAttribute(k_gemm_h<ND, NF, false>,
                             cudaFuncAttributeMaxDynamicSharedMemorySize, DSMEM);
        cudaFuncSetAttribute(k_gemm_h<NF, ND, true>,
                             cudaFuncAttributeMaxDynamicSharedMemorySize, DSMEM);
        smem_set = 1;
    }

    k_prep<<<(NT * ND / 4 + 255) / 256, 256>>>((float4*)out, (const float4*)hidden);
    k_router<<<(NT + 255) / 256, 256>>>(logits);
    k_cvt_w1<<<NE * ND * NF / 4 / 256, 256>>>((const float4*)W1);

    // GEMM1 (z<8) + W2 conversion (z in 8..15) in one launch
    dim3 g1(16, 16, 16);
    k_gemm_h<ND, NF, false><<<g1, 256, DSMEM>>>((const float4*)W2, nullptr);

    dim3 g2(NT / 128, ND / 128, NE);   // (16, 8, 8)
    k_gemm_h<NF, ND, true><<<g2, 256, DSMEM>>>(nullptr, out);
}